// round 14
// baseline (speedup 1.0000x reference)
#include <cuda_runtime.h>
#include <cstdint>
#include <algorithm>

// Problem constants (fixed by dataset shapes)
#define BATCH 4
#define NV    4096
#define NC    128
#define NS    1024   // NV / POOLING_RATE
#define KNBR  4
#define PLF   (NV * 3)        // floats per (b,c) feature plane = 12288
#define PLB   (PLF * 4)       // bytes per plane = 49152

typedef unsigned long long ull;

struct Samp { int s[NS]; };   // 4KB by-value kernel parameter

// -------- device scratch (no allocation allowed) --------
__device__ __align__(16) int g_nbr[BATCH * NS * KNBR];
// Monotonic per-batch arrival counters. NEVER reset: each launch adds exactly
// 128 per batch; wait target derives from the arriving block's own ticket
// ((old & ~127) + 128) -> graph-replay-safe.
__device__ unsigned g_cnt[BATCH];

// -------- JAX threefry2x32 (20 rounds), host-usable --------
__host__ __device__ __forceinline__ void threefry2x32(
    uint32_t k0, uint32_t k1, uint32_t x0, uint32_t x1,
    uint32_t* o0, uint32_t* o1)
{
    uint32_t ks2 = k0 ^ k1 ^ 0x1BD11BDAu;
    x0 += k0; x1 += k1;
#define TF_ROT(x, r) (((x) << (r)) | ((x) >> (32 - (r))))
#define TF_R4(a, b, c, d)                       \
    x0 += x1; x1 = TF_ROT(x1, a); x1 ^= x0;     \
    x0 += x1; x1 = TF_ROT(x1, b); x1 ^= x0;     \
    x0 += x1; x1 = TF_ROT(x1, c); x1 ^= x0;     \
    x0 += x1; x1 = TF_ROT(x1, d); x1 ^= x0;
    TF_R4(13, 15, 26, 6);  x0 += k1;  x1 += ks2 + 1u;
    TF_R4(17, 29, 16, 24); x0 += ks2; x1 += k0 + 2u;
    TF_R4(13, 15, 26, 6);  x0 += k0;  x1 += k1 + 3u;
    TF_R4(17, 29, 16, 24); x0 += k1;  x1 += ks2 + 4u;
    TF_R4(13, 15, 26, 6);  x0 += ks2; x1 += k0 + 5u;
#undef TF_R4
#undef TF_ROT
    *o0 = x0; *o1 = x1;
}

// -------- mbarrier / TMA-bulk helpers --------
__device__ __forceinline__ void mbar_init(void* mbar, unsigned count)
{
    unsigned a = (unsigned)__cvta_generic_to_shared(mbar);
    asm volatile("mbarrier.init.shared.b64 [%0], %1;" :: "r"(a), "r"(count) : "memory");
}
__device__ __forceinline__ void mbar_expect_tx(void* mbar, unsigned bytes)
{
    unsigned a = (unsigned)__cvta_generic_to_shared(mbar);
    asm volatile("mbarrier.arrive.expect_tx.shared.b64 _, [%0], %1;"
                 :: "r"(a), "r"(bytes) : "memory");
}
__device__ __forceinline__ void bulk_g2s(void* dst, const void* src,
                                         unsigned bytes, void* mbar)
{
    unsigned d = (unsigned)__cvta_generic_to_shared(dst);
    unsigned m = (unsigned)__cvta_generic_to_shared(mbar);
    asm volatile(
        "cp.async.bulk.shared::cta.global.mbarrier::complete_tx::bytes "
        "[%0], [%1], %2, [%3];"
        :: "r"(d), "l"(src), "r"(bytes), "r"(m) : "memory");
}
__device__ __forceinline__ void mbar_wait(void* mbar, unsigned parity)
{
    unsigned a = (unsigned)__cvta_generic_to_shared(mbar);
    asm volatile(
        "{\n\t.reg .pred P;\n\t"
        "W%=:\n\t"
        "mbarrier.try_wait.parity.acquire.cta.shared::cta.b64 P, [%0], %1, 0x989680;\n\t"
        "@P bra.uni D%=;\n\t"
        "bra.uni W%=;\n\t"
        "D%=:\n\t}"
        :: "r"(a), "r"(parity) : "memory");
}

// ======================= fused knn + pool ===================================
// Phase A (knn): 8 queries per block; warp w (of 8) scans EIGHTH w (512 pts)
// for all 8 queries, 4 pts/lane/iter (float4 SoA), -2*query coeffs in REGS.
// Scan key = e3 (3-fma) with low-4 mantissa bits = lane-local id. Per-lane
// sorted top-3 -> per-eighth pop-6 -> 48 candidates -> exact rescore
// (validated 4-fma form) + (monotone bits, idx) rank; self = rank 0, dropped.
// Phase B: TMA plane blockIdx.x into dead vertex smem immediately (overlaps
// other blocks' compute), monotonic batch barrier, gather.
// block = 256 (8 warps); grid = 512 (block <-> plane); >=3 blocks/SM.
__global__ __launch_bounds__(256, 3)
void fused_kernel(const float* __restrict__ Vtx, const float* __restrict__ F,
                  float* __restrict__ out, Samp smp)
{
    extern __shared__ __align__(16) float sx[];      // [NV] SoA; reused as plane
    float* sy = sx + NV;
    float* sz = sy + NV;
    int*   cand = (int*)(sz + NV);                   // [8 eighth][8 q][6]
    ull*   kbuf = (ull*)(cand + 384);                // [8][48]
    __shared__ __align__(8) ull mbar;

    int b = blockIdx.x >> 7;
    int qg = blockIdx.x & 127;
    int tid = threadIdx.x;

    if (tid == 0) mbar_init(&mbar, 1);

    // stage vertices SoA: 4 points (3 float4) per thread-iteration
    {
        const float4* vb4 = (const float4*)(Vtx + (size_t)b * NV * 3);
        for (int c = tid; c < NV / 4; c += 256) {
            float4 a = vb4[3 * c], d4 = vb4[3 * c + 1], e4 = vb4[3 * c + 2];
            int p = 4 * c;
            sx[p]     = a.x;  sy[p]     = a.y;  sz[p]     = a.z;
            sx[p + 1] = a.w;  sy[p + 1] = d4.x; sz[p + 1] = d4.y;
            sx[p + 2] = d4.z; sy[p + 2] = d4.w; sz[p + 2] = e4.x;
            sx[p + 3] = e4.y; sy[p + 3] = e4.z; sz[p + 3] = e4.w;
        }
    }
    __syncthreads();

    int sbase = qg * 8;
    // first q-group block per batch also emits vertices_pool (b,1024,3)
    if (qg == 0) {
        for (int t = tid; t < NS * 3; t += 256) {
            int s = t / 3, d = t - 3 * s;
            float v = (d == 0) ? sx[smp.s[s]] : (d == 1) ? sy[smp.s[s]] : sz[smp.s[s]];
            out[(b * NS + s) * 3 + d] = v;
        }
    }

    int warp = tid >> 5;
    int lane = tid & 31;

    // -2*query coefficients in registers
    float mx[8], my[8], mz[8];
#pragma unroll
    for (int qi = 0; qi < 8; ++qi) {
        int n = smp.s[sbase + qi];
        mx[qi] = -2.0f * sx[n];
        my[qi] = -2.0f * sy[n];
        mz[qi] = -2.0f * sz[n];
    }

    const float INF = __int_as_float(0x7f800000);
    float k0[8], k1[8], k2[8];
#pragma unroll
    for (int qi = 0; qi < 8; ++qi) { k0[qi] = INF; k1[qi] = INF; k2[qi] = INF; }

    int base = warp * 512 + lane * 4;   // lane owns 4 consecutive pts, step 128

    // ---- phase A main scan: e3 + key + sorted top-3 insert, 4 pts/iter ----
#pragma unroll
    for (int it = 0; it < 4; ++it) {
        int p = base + it * 128;
        float4 X = *(const float4*)(sx + p);
        float4 Y = *(const float4*)(sy + p);
        float4 Z = *(const float4*)(sz + p);
        float qm0 = fmaf(Z.x, Z.x, fmaf(Y.x, Y.x, X.x * X.x));
        float qm1 = fmaf(Z.y, Z.y, fmaf(Y.y, Y.y, X.y * X.y));
        float qm2 = fmaf(Z.z, Z.z, fmaf(Y.z, Y.z, X.z * X.z));
        float qm3 = fmaf(Z.w, Z.w, fmaf(Y.w, Y.w, X.w * X.w));
        int loc = it * 4;
#pragma unroll
        for (int qi = 0; qi < 8; ++qi) {
            float e0 = fmaf(mz[qi], Z.x, fmaf(my[qi], Y.x, fmaf(mx[qi], X.x, qm0)));
            float f0 = __int_as_float((__float_as_int(e0) & ~15) | loc);
            float a0 = fmaxf(k0[qi], f0); k0[qi] = fminf(k0[qi], f0);
            float a1 = fmaxf(k1[qi], a0); k1[qi] = fminf(k1[qi], a0);
            k2[qi] = fminf(k2[qi], a1);

            float e1 = fmaf(mz[qi], Z.y, fmaf(my[qi], Y.y, fmaf(mx[qi], X.y, qm1)));
            float f1 = __int_as_float((__float_as_int(e1) & ~15) | (loc + 1));
            float b0 = fmaxf(k0[qi], f1); k0[qi] = fminf(k0[qi], f1);
            float b1 = fmaxf(k1[qi], b0); k1[qi] = fminf(k1[qi], b0);
            k2[qi] = fminf(k2[qi], b1);

            float e2 = fmaf(mz[qi], Z.z, fmaf(my[qi], Y.z, fmaf(mx[qi], X.z, qm2)));
            float f2 = __int_as_float((__float_as_int(e2) & ~15) | (loc + 2));
            float c0 = fmaxf(k0[qi], f2); k0[qi] = fminf(k0[qi], f2);
            float c1 = fmaxf(k1[qi], c0); k1[qi] = fminf(k1[qi], c0);
            k2[qi] = fminf(k2[qi], c1);

            float e3 = fmaf(mz[qi], Z.w, fmaf(my[qi], Y.w, fmaf(mx[qi], X.w, qm3)));
            float f3 = __int_as_float((__float_as_int(e3) & ~15) | (loc + 3));
            float d0 = fmaxf(k0[qi], f3); k0[qi] = fminf(k0[qi], f3);
            float d1 = fmaxf(k1[qi], d0); k1[qi] = fminf(k1[qi], d0);
            k2[qi] = fminf(k2[qi], d1);
        }
    }

    // ---- per-eighth pop-6 with index reconstruction ----
#pragma unroll
    for (int qi = 0; qi < 8; ++qi) {
        float a0 = k0[qi], a1 = k1[qi], a2 = k2[qi];
#pragma unroll
        for (int t = 0; t < 6; ++t) {
            float mn = a0;
#pragma unroll
            for (int off = 16; off; off >>= 1)
                mn = fminf(mn, __shfl_xor_sync(0xffffffffu, mn, off));
            unsigned bal = __ballot_sync(0xffffffffu, a0 == mn);
            int leader = __ffs(bal) - 1;
            if (lane == leader) {
                a0 = a1; a1 = a2; a2 = INF;
                int loc = __float_as_int(mn) & 15;
                int m = warp * 512 + ((loc >> 2) << 7) + (leader << 2) + (loc & 3);
                cand[(warp * 8 + qi) * 6 + t] = m;
            }
        }
    }
    __syncthreads();

    // ---- exact rescore + rank of 48 candidates; warp w -> query w ----------
    {
        int q = warp;
        int nq = smp.s[sbase + q];
        float qxx = sx[nq], qyy = sy[nq], qzz = sz[nq];
        ull key0 = ~0ULL, key1 = ~0ULL;
        int m0 = -1, m1 = -1;
        {
            int s = lane;               // slot 0..31
            int ei = s / 6, t = s - ei * 6;
            m0 = cand[(ei * 8 + q) * 6 + t];
            float xm = sx[m0], ym = sy[m0], zm = sz[m0];
            float qm = fmaf(zm, zm, fmaf(ym, ym, xm * xm));
            float e = fmaf(-2.0f, fmaf(qzz, zm, fmaf(qyy, ym, qxx * xm)), qm);
            unsigned kb = __float_as_uint(e);
            kb ^= (kb & 0x80000000u) ? 0xffffffffu : 0x80000000u;
            key0 = ((ull)kb << 32) | (unsigned)m0;
            kbuf[q * 48 + s] = key0;
        }
        if (lane < 16) {
            int s = lane + 32;          // slot 32..47
            int ei = s / 6, t = s - ei * 6;
            m1 = cand[(ei * 8 + q) * 6 + t];
            float xm = sx[m1], ym = sy[m1], zm = sz[m1];
            float qm = fmaf(zm, zm, fmaf(ym, ym, xm * xm));
            float e = fmaf(-2.0f, fmaf(qzz, zm, fmaf(qyy, ym, qxx * xm)), qm);
            unsigned kb = __float_as_uint(e);
            kb ^= (kb & 0x80000000u) ? 0xffffffffu : 0x80000000u;
            key1 = ((ull)kb << 32) | (unsigned)m1;
            kbuf[q * 48 + s] = key1;
        }
        __syncwarp();
        int r0 = 0, r1 = 0;
        for (int j = 0; j < 48; ++j) {
            ull o = kbuf[q * 48 + j];    // broadcast LDS
            r0 += (o < key0); r1 += (o < key1);
        }
        int obase = (b * NS + (sbase + q)) * KNBR;
        if (r0 >= 1 && r0 <= KNBR) g_nbr[obase + r0 - 1] = m0;
        if (lane < 16 && r1 >= 1 && r1 <= KNBR) g_nbr[obase + r1 - 1] = m1;
    }

    // ================= phase B: pool plane blockIdx.x =======================
    __syncthreads();   // all warps done with vertex smem + g_nbr writes

    int pl = blockIdx.x;
    if (tid == 0) {
        mbar_expect_tx(&mbar, PLB);
        bulk_g2s(sx, F + (size_t)pl * PLF, PLB, &mbar);   // overwrites verts
        __threadfence();                                   // release g_nbr
        unsigned o = atomicAdd(&g_cnt[b], 1u);
        unsigned target = (o & ~127u) + 128u;
        for (;;) {
            unsigned cur;
            asm volatile("ld.acquire.gpu.global.u32 %0, [%1];"
                         : "=r"(cur) : "l"(&g_cnt[b]) : "memory");
            if (cur >= target) break;
            __nanosleep(128);
        }
    }
    __syncthreads();

    // prefetch neighbor indices (cross-block data: bypass L1)
    const int4* nbr4 = (const int4*)g_nbr + b * NS;
    int4 nb[4];
#pragma unroll
    for (int i = 0; i < 4; ++i)
        nb[i] = __ldcg(&nbr4[i * 256 + tid]);

    mbar_wait(&mbar, 0);   // plane resident in smem

    float* fout = out + BATCH * NS * 3 + (size_t)pl * NS * 3;
#pragma unroll
    for (int i = 0; i < 4; ++i) {
        int t = i * 256 + tid;
        int j0 = nb[i].x * 3, j1 = nb[i].y * 3, j2 = nb[i].z * 3, j3 = nb[i].w * 3;
        float o0 = fmaxf(fmaxf(sx[j0],     sx[j1]),     fmaxf(sx[j2],     sx[j3]));
        float o1 = fmaxf(fmaxf(sx[j0 + 1], sx[j1 + 1]), fmaxf(sx[j2 + 1], sx[j3 + 1]));
        float o2 = fmaxf(fmaxf(sx[j0 + 2], sx[j1 + 2]), fmaxf(sx[j2 + 2], sx[j3 + 2]));
        fout[t * 3]     = o0;
        fout[t * 3 + 1] = o1;
        fout[t * 3 + 2] = o2;
    }
}

// ======================= host entry =========================================
extern "C" void kernel_launch(void* const* d_in, const int* in_sizes, int n_in,
                              void* d_out, int out_size)
{
    const float* Vtx;
    const float* F;
    if (in_sizes[0] == BATCH * NV * 3) {
        Vtx = (const float*)d_in[0];
        F   = (const float*)d_in[1];
    } else {
        Vtx = (const float*)d_in[1];
        F   = (const float*)d_in[0];
    }

    // ---- host-side permutation (pure arithmetic; runs at capture time) ----
    uint32_t k10, k11, sub_lo[2], sub_hi[2];
    threefry2x32(0u, 42u, 0u, 0u, &k10, &k11);             // round-1 carry key
    threefry2x32(0u, 42u, 0u, 1u, &sub_lo[0], &sub_hi[0]); // round-1 subkey
    threefry2x32(k10, k11, 0u, 1u, &sub_lo[1], &sub_hi[1]);// round-2 subkey

    static ull pk[NV];
    static int rk[2][NV];
    for (int r = 0; r < 2; ++r) {
        for (int i = 0; i < NV; ++i) {
            uint32_t w0, w1;
            threefry2x32(sub_lo[r], sub_hi[r], 0u, (uint32_t)i, &w0, &w1);
            pk[i] = ((ull)(w0 ^ w1) << 32) | (uint32_t)i;
        }
        std::sort(pk, pk + NV);   // index in low bits -> stable rank
        for (int j = 0; j < NV; ++j) rk[r][(uint32_t)pk[j]] = j;
    }
    static Samp h_samp;
    for (int i = 0; i < NV; ++i) {
        int pos = rk[1][rk[0][i]];
        if (pos < NS) h_samp.s[pos] = i;
    }

    int smem = NV * 3 * (int)sizeof(float)      // vertices / plane
             + 384 * (int)sizeof(int)           // cand
             + 8 * 48 * (int)sizeof(ull);       // kbuf
    cudaFuncSetAttribute(fused_kernel,
                         cudaFuncAttributeMaxDynamicSharedMemorySize, smem);

    fused_kernel<<<512, 256, smem>>>(Vtx, F, (float*)d_out, h_samp);
}

// round 15
// speedup vs baseline: 1.2065x; 1.2065x over previous
#include <cuda_runtime.h>
#include <cstdint>
#include <algorithm>

// Problem constants (fixed by dataset shapes)
#define BATCH 4
#define NV    4096
#define NC    128
#define NS    1024   // NV / POOLING_RATE
#define KNBR  4
#define PLF   (NV * 3)        // floats per (b,c) feature plane = 12288
#define PLB   (PLF * 4)       // bytes per plane = 49152

typedef unsigned long long ull;

struct Samp { int s[NS]; };   // 4KB by-value kernel parameter

// -------- device scratch (no allocation allowed) --------
__device__ __align__(16) int g_nbr[BATCH * NS * KNBR];
// Monotonic per-batch arrival counters. NEVER reset: each launch adds exactly
// 128 per batch; wait target derives from the arriving block's own ticket
// ((old & ~127) + 128) -> graph-replay-safe.
__device__ unsigned g_cnt[BATCH];

// -------- JAX threefry2x32 (20 rounds), host-usable --------
__host__ __device__ __forceinline__ void threefry2x32(
    uint32_t k0, uint32_t k1, uint32_t x0, uint32_t x1,
    uint32_t* o0, uint32_t* o1)
{
    uint32_t ks2 = k0 ^ k1 ^ 0x1BD11BDAu;
    x0 += k0; x1 += k1;
#define TF_ROT(x, r) (((x) << (r)) | ((x) >> (32 - (r))))
#define TF_R4(a, b, c, d)                       \
    x0 += x1; x1 = TF_ROT(x1, a); x1 ^= x0;     \
    x0 += x1; x1 = TF_ROT(x1, b); x1 ^= x0;     \
    x0 += x1; x1 = TF_ROT(x1, c); x1 ^= x0;     \
    x0 += x1; x1 = TF_ROT(x1, d); x1 ^= x0;
    TF_R4(13, 15, 26, 6);  x0 += k1;  x1 += ks2 + 1u;
    TF_R4(17, 29, 16, 24); x0 += ks2; x1 += k0 + 2u;
    TF_R4(13, 15, 26, 6);  x0 += k0;  x1 += k1 + 3u;
    TF_R4(17, 29, 16, 24); x0 += k1;  x1 += ks2 + 4u;
    TF_R4(13, 15, 26, 6);  x0 += ks2; x1 += k0 + 5u;
#undef TF_R4
#undef TF_ROT
    *o0 = x0; *o1 = x1;
}

// -------- mbarrier / TMA-bulk helpers --------
__device__ __forceinline__ void mbar_init(void* mbar, unsigned count)
{
    unsigned a = (unsigned)__cvta_generic_to_shared(mbar);
    asm volatile("mbarrier.init.shared.b64 [%0], %1;" :: "r"(a), "r"(count) : "memory");
}
__device__ __forceinline__ void mbar_expect_tx(void* mbar, unsigned bytes)
{
    unsigned a = (unsigned)__cvta_generic_to_shared(mbar);
    asm volatile("mbarrier.arrive.expect_tx.shared.b64 _, [%0], %1;"
                 :: "r"(a), "r"(bytes) : "memory");
}
__device__ __forceinline__ void bulk_g2s(void* dst, const void* src,
                                         unsigned bytes, void* mbar)
{
    unsigned d = (unsigned)__cvta_generic_to_shared(dst);
    unsigned m = (unsigned)__cvta_generic_to_shared(mbar);
    asm volatile(
        "cp.async.bulk.shared::cta.global.mbarrier::complete_tx::bytes "
        "[%0], [%1], %2, [%3];"
        :: "r"(d), "l"(src), "r"(bytes), "r"(m) : "memory");
}
__device__ __forceinline__ void mbar_wait(void* mbar, unsigned parity)
{
    unsigned a = (unsigned)__cvta_generic_to_shared(mbar);
    asm volatile(
        "{\n\t.reg .pred P;\n\t"
        "W%=:\n\t"
        "mbarrier.try_wait.parity.acquire.cta.shared::cta.b64 P, [%0], %1, 0x989680;\n\t"
        "@P bra.uni D%=;\n\t"
        "bra.uni W%=;\n\t"
        "D%=:\n\t}"
        :: "r"(a), "r"(parity) : "memory");
}

// ======================= fused knn + pool ===================================
// Phase A (knn): 8 queries per block; warp w (of 4) scans QUARTER w (1024
// pts) for all 8 queries, 4 pts/lane/iter (float4 SoA), -2*query coeffs in
// registers. Scan key = e3 (3-fma) with low-5 mantissa bits = lane-local id
// (<=31 ulp perturb, id recoverable). Per-lane sorted top-3 -> per-quarter
// pop-6 -> 24 candidates -> exact rescore (validated 4-fma form) + (monotone
// bits, idx) rank; self = rank 0, dropped.
// Phase B: TMA plane blockIdx.x into the dead vertex smem immediately
// (overlaps other blocks' knn compute), monotonic batch barrier, gather.
// block = 128 (4 warps); grid = 512 (block <-> plane); 4 blocks/SM (smem).
__global__ __launch_bounds__(128)
void fused_kernel(const float* __restrict__ Vtx, const float* __restrict__ F,
                  float* __restrict__ out, Samp smp)
{
    extern __shared__ __align__(16) float sx[];      // [NV] SoA; reused as plane
    float* sy = sx + NV;
    float* sz = sy + NV;
    int*   cand = (int*)(sz + NV);                   // [4][8][6] = 192 ints
    ull*   kbuf = (ull*)(cand + 192);                // [8][24]
    __shared__ __align__(8) ull mbar;

    int b = blockIdx.x >> 7;
    int qg = blockIdx.x & 127;
    int tid = threadIdx.x;

    if (tid == 0) mbar_init(&mbar, 1);

    // stage vertices SoA: 4 points (3 float4) per thread-iteration
    {
        const float4* vb4 = (const float4*)(Vtx + (size_t)b * NV * 3);
        for (int c = tid; c < NV / 4; c += 128) {
            float4 a = vb4[3 * c], d4 = vb4[3 * c + 1], e4 = vb4[3 * c + 2];
            int p = 4 * c;
            sx[p]     = a.x;  sy[p]     = a.y;  sz[p]     = a.z;
            sx[p + 1] = a.w;  sy[p + 1] = d4.x; sz[p + 1] = d4.y;
            sx[p + 2] = d4.z; sy[p + 2] = d4.w; sz[p + 2] = e4.x;
            sx[p + 3] = e4.y; sy[p + 3] = e4.z; sz[p + 3] = e4.w;
        }
    }
    __syncthreads();

    int sbase = qg * 8;
    // first q-group block per batch also emits vertices_pool (b,1024,3)
    if (qg == 0) {
        for (int t = tid; t < NS * 3; t += 128) {
            int s = t / 3, d = t - 3 * s;
            float v = (d == 0) ? sx[smp.s[s]] : (d == 1) ? sy[smp.s[s]] : sz[smp.s[s]];
            out[(b * NS + s) * 3 + d] = v;
        }
    }

    int warp = tid >> 5;
    int lane = tid & 31;

    // -2*query coefficients in registers (scan uses these; rescore re-reads
    // raw coords from smem and uses the validated 4-fma form)
    float mx[8], my[8], mz[8];
#pragma unroll
    for (int qi = 0; qi < 8; ++qi) {
        int n = smp.s[sbase + qi];
        mx[qi] = -2.0f * sx[n];
        my[qi] = -2.0f * sy[n];
        mz[qi] = -2.0f * sz[n];
    }

    const float INF = __int_as_float(0x7f800000);
    float k0[8], k1[8], k2[8];
#pragma unroll
    for (int qi = 0; qi < 8; ++qi) { k0[qi] = INF; k1[qi] = INF; k2[qi] = INF; }

    int base = warp * 1024 + lane * 4;   // lane owns 4 consecutive pts, step 128

    // ---- phase A main scan: e3 + key + sorted top-3 insert, 4 pts/iter ----
#pragma unroll 2
    for (int it = 0; it < 8; ++it) {
        int p = base + it * 128;
        float4 X = *(const float4*)(sx + p);
        float4 Y = *(const float4*)(sy + p);
        float4 Z = *(const float4*)(sz + p);
        float qm0 = fmaf(Z.x, Z.x, fmaf(Y.x, Y.x, X.x * X.x));
        float qm1 = fmaf(Z.y, Z.y, fmaf(Y.y, Y.y, X.y * X.y));
        float qm2 = fmaf(Z.z, Z.z, fmaf(Y.z, Y.z, X.z * X.z));
        float qm3 = fmaf(Z.w, Z.w, fmaf(Y.w, Y.w, X.w * X.w));
        int loc = it * 4;
#pragma unroll
        for (int qi = 0; qi < 8; ++qi) {
            float e0 = fmaf(mz[qi], Z.x, fmaf(my[qi], Y.x, fmaf(mx[qi], X.x, qm0)));
            float f0 = __int_as_float((__float_as_int(e0) & ~31) | loc);
            float a0 = fmaxf(k0[qi], f0); k0[qi] = fminf(k0[qi], f0);
            float a1 = fmaxf(k1[qi], a0); k1[qi] = fminf(k1[qi], a0);
            k2[qi] = fminf(k2[qi], a1);

            float e1 = fmaf(mz[qi], Z.y, fmaf(my[qi], Y.y, fmaf(mx[qi], X.y, qm1)));
            float f1 = __int_as_float((__float_as_int(e1) & ~31) | (loc + 1));
            float b0 = fmaxf(k0[qi], f1); k0[qi] = fminf(k0[qi], f1);
            float b1 = fmaxf(k1[qi], b0); k1[qi] = fminf(k1[qi], b0);
            k2[qi] = fminf(k2[qi], b1);

            float e2 = fmaf(mz[qi], Z.z, fmaf(my[qi], Y.z, fmaf(mx[qi], X.z, qm2)));
            float f2 = __int_as_float((__float_as_int(e2) & ~31) | (loc + 2));
            float c0 = fmaxf(k0[qi], f2); k0[qi] = fminf(k0[qi], f2);
            float c1 = fmaxf(k1[qi], c0); k1[qi] = fminf(k1[qi], c0);
            k2[qi] = fminf(k2[qi], c1);

            float e3 = fmaf(mz[qi], Z.w, fmaf(my[qi], Y.w, fmaf(mx[qi], X.w, qm3)));
            float f3 = __int_as_float((__float_as_int(e3) & ~31) | (loc + 3));
            float d0 = fmaxf(k0[qi], f3); k0[qi] = fminf(k0[qi], f3);
            float d1 = fmaxf(k1[qi], d0); k1[qi] = fminf(k1[qi], d0);
            k2[qi] = fminf(k2[qi], d1);
        }
    }

    // ---- per-quarter pop-6 with index reconstruction ----
#pragma unroll
    for (int qi = 0; qi < 8; ++qi) {
        float a0 = k0[qi], a1 = k1[qi], a2 = k2[qi];
#pragma unroll
        for (int t = 0; t < 6; ++t) {
            float mn = a0;
#pragma unroll
            for (int off = 16; off; off >>= 1)
                mn = fminf(mn, __shfl_xor_sync(0xffffffffu, mn, off));
            unsigned bal = __ballot_sync(0xffffffffu, a0 == mn);
            int leader = __ffs(bal) - 1;
            if (lane == leader) {
                a0 = a1; a1 = a2; a2 = INF;
                int loc = __float_as_int(mn) & 31;
                int m = warp * 1024 + ((loc >> 2) << 7) + (leader << 2) + (loc & 3);
                cand[warp * 48 + qi * 6 + t] = m;
            }
        }
    }
    __syncthreads();

    // ---- exact rescore + rank of 24 candidates; warp w -> queries 2w,2w+1 --
#pragma unroll
    for (int kq = 0; kq < 2; ++kq) {
        int q = warp * 2 + kq;
        int nq = smp.s[sbase + q];
        float qxx = sx[nq], qyy = sy[nq], qzz = sz[nq];
        ull key = ~0ULL;
        int m = -1;
        if (lane < 24) {
            int quarter = lane / 6;
            int slot = lane - quarter * 6;
            m = cand[quarter * 48 + q * 6 + slot];
            float xm = sx[m], ym = sy[m], zm = sz[m];
            float qm = fmaf(zm, zm, fmaf(ym, ym, xm * xm));
            float e = fmaf(-2.0f, fmaf(qzz, zm, fmaf(qyy, ym, qxx * xm)), qm);
            unsigned kb = __float_as_uint(e);
            kb ^= (kb & 0x80000000u) ? 0xffffffffu : 0x80000000u; // monotone
            key = ((ull)kb << 32) | (unsigned)m;
            kbuf[q * 24 + lane] = key;
        }
        __syncwarp();
        int r = 0;
        for (int j = 0; j < 24; ++j) {
            ull o = kbuf[q * 24 + j];    // broadcast LDS
            r += (o < key);
        }
        if (lane < 24 && r >= 1 && r <= KNBR)
            g_nbr[(b * NS + (sbase + q)) * KNBR + (r - 1)] = m;
        __syncwarp();
    }

    // ================= phase B: pool plane blockIdx.x =======================
    __syncthreads();   // all warps done with vertex smem + g_nbr writes

    int pl = blockIdx.x;
    if (tid == 0) {
        mbar_expect_tx(&mbar, PLB);
        bulk_g2s(sx, F + (size_t)pl * PLF, PLB, &mbar);   // overwrites verts
        __threadfence();                                   // release g_nbr
        unsigned o = atomicAdd(&g_cnt[b], 1u);
        unsigned target = (o & ~127u) + 128u;
        for (;;) {
            unsigned cur;
            asm volatile("ld.acquire.gpu.global.u32 %0, [%1];"
                         : "=r"(cur) : "l"(&g_cnt[b]) : "memory");
            if (cur >= target) break;
            __nanosleep(128);
        }
    }
    __syncthreads();

    // prefetch neighbor indices (cross-block data: bypass L1)
    const int4* nbr4 = (const int4*)g_nbr + b * NS;
    int4 nb[8];
#pragma unroll
    for (int i = 0; i < 8; ++i)
        nb[i] = __ldcg(&nbr4[i * 128 + tid]);

    mbar_wait(&mbar, 0);   // plane resident in smem

    float* fout = out + BATCH * NS * 3 + (size_t)pl * NS * 3;
#pragma unroll
    for (int i = 0; i < 8; ++i) {
        int t = i * 128 + tid;
        int j0 = nb[i].x * 3, j1 = nb[i].y * 3, j2 = nb[i].z * 3, j3 = nb[i].w * 3;
        float o0 = fmaxf(fmaxf(sx[j0],     sx[j1]),     fmaxf(sx[j2],     sx[j3]));
        float o1 = fmaxf(fmaxf(sx[j0 + 1], sx[j1 + 1]), fmaxf(sx[j2 + 1], sx[j3 + 1]));
        float o2 = fmaxf(fmaxf(sx[j0 + 2], sx[j1 + 2]), fmaxf(sx[j2 + 2], sx[j3 + 2]));
        fout[t * 3]     = o0;
        fout[t * 3 + 1] = o1;
        fout[t * 3 + 2] = o2;
    }
}

// ======================= host entry =========================================
extern "C" void kernel_launch(void* const* d_in, const int* in_sizes, int n_in,
                              void* d_out, int out_size)
{
    const float* Vtx;
    const float* F;
    if (in_sizes[0] == BATCH * NV * 3) {
        Vtx = (const float*)d_in[0];
        F   = (const float*)d_in[1];
    } else {
        Vtx = (const float*)d_in[1];
        F   = (const float*)d_in[0];
    }

    // ---- host-side permutation (pure arithmetic; runs at capture time) ----
    uint32_t k10, k11, sub_lo[2], sub_hi[2];
    threefry2x32(0u, 42u, 0u, 0u, &k10, &k11);             // round-1 carry key
    threefry2x32(0u, 42u, 0u, 1u, &sub_lo[0], &sub_hi[0]); // round-1 subkey
    threefry2x32(k10, k11, 0u, 1u, &sub_lo[1], &sub_hi[1]);// round-2 subkey

    static ull pk[NV];
    static int rk[2][NV];
    for (int r = 0; r < 2; ++r) {
        for (int i = 0; i < NV; ++i) {
            uint32_t w0, w1;
            threefry2x32(sub_lo[r], sub_hi[r], 0u, (uint32_t)i, &w0, &w1);
            pk[i] = ((ull)(w0 ^ w1) << 32) | (uint32_t)i;
        }
        std::sort(pk, pk + NV);   // index in low bits -> stable rank
        for (int j = 0; j < NV; ++j) rk[r][(uint32_t)pk[j]] = j;
    }
    static Samp h_samp;
    for (int i = 0; i < NV; ++i) {
        int pos = rk[1][rk[0][i]];
        if (pos < NS) h_samp.s[pos] = i;
    }

    int smem = NV * 3 * (int)sizeof(float)      // vertices / plane
             + 192 * (int)sizeof(int)           // cand
             + 8 * 24 * (int)sizeof(ull);       // kbuf
    cudaFuncSetAttribute(fused_kernel,
                         cudaFuncAttributeMaxDynamicSharedMemorySize, smem);

    fused_kernel<<<512, 128, smem>>>(Vtx, F, (float*)d_out, h_samp);
}